// round 7
// baseline (speedup 1.0000x reference)
#include <cuda_runtime.h>
#include <cstdint>
#include <cstddef>

// Problem constants
#define T_STEPS   101
#define B_SZ      16384
#define IN_DIM    40
#define HID       300
#define NPAD      320
#define OUT_DIM   12
#define HALF_N    160          // neurons per warp (N-split)
#define SEG       160          // list segment capacity (u16)

#define WARPS_PER_BLK   8      // 4 pairs
#define THREADS_PER_BLK 256
#define PAIRS_PER_BLK   4
#define ROWS_PER_PAIR   4
#define ROWS_PER_BLK    16
#define NUM_BLKS        (B_SZ / ROWS_PER_BLK)   // 1024

// Transposed, padded recurrent/ff weights (global, L2-resident: 384KB each)
__device__ float g_WhT[HID * NPAD];   // g_WhT[k*NPAD + i] = Wh[i*HID + k]
__device__ float g_W2T[HID * NPAD];

__global__ void prep_kernel(const float* __restrict__ Wh,
                            const float* __restrict__ W2) {
    int idx = blockIdx.x * blockDim.x + threadIdx.x;
    const int total = HID * NPAD;
    if (idx < total) {
        int k = idx / NPAD;
        int i = idx % NPAD;
        float wh = 0.0f, w2 = 0.0f;
        if (i < HID) {
            wh = Wh[i * HID + k];
            w2 = W2[i * HID + k];
        }
        g_WhT[idx] = wh;
        g_W2T[idx] = w2;
    }
}

// ---- packed f32x2 helpers ----
__device__ __forceinline__ unsigned long long pk2(float lo, float hi) {
    unsigned long long r;
    asm("mov.b64 %0, {%1, %2};" : "=l"(r) : "f"(lo), "f"(hi));
    return r;
}
__device__ __forceinline__ void upk2(unsigned long long v, float& lo, float& hi) {
    asm("mov.b64 {%0, %1}, %2;" : "=f"(lo), "=f"(hi) : "l"(v));
}
__device__ __forceinline__ void ffma2(unsigned long long& acc,
                                      unsigned long long a, unsigned long long b) {
    asm("fma.rn.f32x2 %0, %1, %2, %0;" : "+l"(acc) : "l"(a), "l"(b));
}
__device__ __forceinline__ void fadd2(unsigned long long& acc, unsigned long long a) {
    asm("add.rn.f32x2 %0, %0, %1;" : "+l"(acc) : "l"(a));
}
__device__ __forceinline__ unsigned long long fsub2(unsigned long long a,
                                                    unsigned long long b) {
    unsigned long long d;
    asm("sub.rn.f32x2 %0, %1, %2;" : "=l"(d) : "l"(a), "l"(b));
    return d;
}
__device__ __forceinline__ void pair_bar(int pid) {
    asm volatile("bar.sync %0, 64;" :: "r"(pid + 1) : "memory");
}

// Per-warp neuron layout (half h, base = 160h), per lane L:
//  pair p=0: (base+4L, base+4L+1)   pair p=1: (base+4L+2, base+4L+3)   [base..base+127]
//  scalar:   base+128+L                                                [base+128..base+159]

// gather-add one spike row's half-slice into cur pairs + scalar
__device__ __forceinline__ void gather_half(const float* __restrict__ w0,
                                            int L, unsigned long long* c, float& cs) {
    ulonglong2 a0 = *(const ulonglong2*)(w0 + 4 * L);
    float s0 = w0[128 + L];
    fadd2(c[0], a0.x);
    fadd2(c[1], a0.y);
    cs += s0;
}

__global__ void __launch_bounds__(THREADS_PER_BLK, 2)
snn_kernel(const float* __restrict__ x,
           const float* __restrict__ W1,
           const float* __restrict__ b1,
           const float* __restrict__ bh,
           const float* __restrict__ b2,
           const float* __restrict__ W3,
           const float* __restrict__ b3,
           float* __restrict__ out) {
    extern __shared__ char smem_raw[];
    float* W1Ts = (float*)smem_raw;                 // [IN_DIM][NPAD]  51200 B
    float* bsum = W1Ts + IN_DIM * NPAD;             // [NPAD]
    float* b2s  = bsum + NPAD;                      // [NPAD]
    float* obuf = b2s + NPAD;                       // [16][2][12] partials
    unsigned short* al = (unsigned short*)(obuf + ROWS_PER_BLK * 2 * OUT_DIM);
    // al: [16 rows][2 segs][SEG] u16 = 10240 B
    int* scnt = (int*)(al + ROWS_PER_BLK * 2 * SEG); // [16][2] counts

    const int tid = threadIdx.x;

    for (int idx = tid; idx < IN_DIM * NPAD; idx += THREADS_PER_BLK) {
        int k = idx / NPAD;
        int hcol = idx % NPAD;
        W1Ts[idx] = (hcol < HID) ? W1[hcol * IN_DIM + k] : 0.0f;
    }
    for (int n = tid; n < NPAD; n += THREADS_PER_BLK) {
        bsum[n] = (n < HID) ? (b1[n] + bh[n]) : 0.0f;
        b2s[n]  = (n < HID) ? b2[n] : 0.0f;
    }
    if (tid < ROWS_PER_BLK * 2) scnt[tid] = 0;
    __syncthreads();

    const int w   = tid >> 5;
    const int L   = tid & 31;
    const int pid = w >> 1;          // pair id 0..3
    const int h   = w & 1;           // neuron half
    const int base = h * HALF_N;
    const int rl0  = pid * ROWS_PER_PAIR;            // local row base
    const int grow0 = blockIdx.x * ROWS_PER_BLK + rl0;
    unsigned short* alp = al + rl0 * (2 * SEG);      // this pair's 4 rows
    int* scp = scnt + rl0 * 2;

    // LIF states: 2 packed pairs + 1 scalar per row (own 160-neuron half)
    unsigned long long v1p[ROWS_PER_PAIR][2], v2p[ROWS_PER_PAIR][2];
    unsigned long long cur[ROWS_PER_PAIR][2];
    float v1s[ROWS_PER_PAIR], v2s[ROWS_PER_PAIR], curs[ROWS_PER_PAIR];
    unsigned c2a[ROWS_PER_PAIR], c2b[ROWS_PER_PAIR];
#pragma unroll
    for (int r = 0; r < ROWS_PER_PAIR; r++) {
        v1p[r][0] = v1p[r][1] = 0ull;
        v2p[r][0] = v2p[r][1] = 0ull;
        v1s[r] = v2s[r] = 0.0f;
        c2a[r] = 0u; c2b[r] = 0u;
    }
    const unsigned long long HALF2 = 0x3F0000003F000000ull;
    const unsigned lt_mask = (1u << L) - 1u;

    const float* xptr = x + (size_t)grow0 * IN_DIM;
    const size_t xstep = (size_t)B_SZ * IN_DIM;

#pragma unroll 1
    for (int t = 0; t < T_STEPS; t++) {
        // ---- load x for 4 rows (both warps of pair load; L1-shared) ----
        float xa[ROWS_PER_PAIR], xb[ROWS_PER_PAIR];
#pragma unroll
        for (int r = 0; r < ROWS_PER_PAIR; r++) {
            xa[r] = xptr[r * IN_DIM + L];
            xb[r] = (L < 8) ? xptr[r * IN_DIM + 32 + L] : 0.0f;
        }
        xptr += xstep;

        // ---- cur = bias (own half) ----
        {
            ulonglong2 bA = *(const ulonglong2*)(bsum + base + 4 * L);
            float bS = bsum[base + 128 + L];
#pragma unroll
            for (int r = 0; r < ROWS_PER_PAIR; r++) {
                cur[r][0] = bA.x; cur[r][1] = bA.y; curs[r] = bS;
            }
        }

        // ---- dense x @ W1^T, own 160-neuron half, 4 rows ----
#pragma unroll 4
        for (int k = 0; k < 32; k++) {
            const float* wr = W1Ts + k * NPAD + base;
            ulonglong2 wA = *(const ulonglong2*)(wr + 4 * L);
            float wS = wr[128 + L];
#pragma unroll
            for (int r = 0; r < ROWS_PER_PAIR; r++) {
                float xv = __shfl_sync(0xffffffffu, xa[r], k);
                unsigned long long xp = pk2(xv, xv);
                ffma2(cur[r][0], xp, wA.x);
                ffma2(cur[r][1], xp, wA.y);
                curs[r] = fmaf(xv, wS, curs[r]);
            }
        }
#pragma unroll
        for (int k = 0; k < 8; k++) {
            const float* wr = W1Ts + (32 + k) * NPAD + base;
            ulonglong2 wA = *(const ulonglong2*)(wr + 4 * L);
            float wS = wr[128 + L];
#pragma unroll
            for (int r = 0; r < ROWS_PER_PAIR; r++) {
                float xv = __shfl_sync(0xffffffffu, xb[r], k);
                unsigned long long xp = pk2(xv, xv);
                ffma2(cur[r][0], xp, wA.x);
                ffma2(cur[r][1], xp, wA.y);
                curs[r] = fmaf(xv, wS, curs[r]);
            }
        }

        // ---- recurrent gathers: prev-step lists (both segments), own half ----
#pragma unroll
        for (int r = 0; r < ROWS_PER_PAIR; r++) {
#pragma unroll
            for (int sg = 0; sg < 2; sg++) {
                const unsigned short* lr = alp + r * (2 * SEG) + sg * SEG;
                const int cn = scp[r * 2 + sg];
                int i = 0;
                for (; i + 2 <= cn; i += 2) {
                    gather_half(g_WhT + (int)lr[i] * NPAD + base, L, cur[r], curs[r]);
                    gather_half(g_WhT + (int)lr[i + 1] * NPAD + base, L, cur[r], curs[r]);
                }
                if (i < cn)
                    gather_half(g_WhT + (int)lr[i] * NPAD + base, L, cur[r], curs[r]);
            }
        }
        pair_bar(pid);   // old lists fully consumed by both warps

        // ---- LIF 1 (own half) + write own list segment ----
#pragma unroll
        for (int r = 0; r < ROWS_PER_PAIR; r++) {
            unsigned short* seg = alp + r * (2 * SEG) + h * SEG;
            int nc = 0;
#pragma unroll
            for (int p = 0; p < 2; p++) {
                unsigned long long d = fsub2(cur[r][p], v1p[r][p]);
                unsigned long long vn = v1p[r][p];
                ffma2(vn, d, HALF2);
                float lo, hi;
                upk2(vn, lo, hi);
                bool s0 = (lo >= 1.0f), s1 = (hi >= 1.0f);
                v1p[r][p] = pk2(s0 ? 0.0f : lo, s1 ? 0.0f : hi);
                int nb = base + 4 * L + 2 * p;
                unsigned m0 = __ballot_sync(0xffffffffu, s0);
                if (s0) seg[nc + __popc(m0 & lt_mask)] = (unsigned short)nb;
                nc += __popc(m0);
                unsigned m1 = __ballot_sync(0xffffffffu, s1);
                if (s1) seg[nc + __popc(m1 & lt_mask)] = (unsigned short)(nb + 1);
                nc += __popc(m1);
            }
            {
                float v = v1s[r] + (curs[r] - v1s[r]) * 0.5f;
                bool s = (v >= 1.0f);
                v1s[r] = s ? 0.0f : v;
                unsigned m = __ballot_sync(0xffffffffu, s);
                if (s) seg[nc + __popc(m & lt_mask)] = (unsigned short)(base + 128 + L);
                nc += __popc(m);
            }
            if (L == 0) scp[r * 2 + h] = nc;
        }
        pair_bar(pid);   // new lists + counts visible to both warps

        // ---- layer 2: bias + gather W2^T (both segments), own half ----
        {
            ulonglong2 bA = *(const ulonglong2*)(b2s + base + 4 * L);
            float bS = b2s[base + 128 + L];
#pragma unroll
            for (int r = 0; r < ROWS_PER_PAIR; r++) {
                cur[r][0] = bA.x; cur[r][1] = bA.y; curs[r] = bS;
            }
        }
#pragma unroll
        for (int r = 0; r < ROWS_PER_PAIR; r++) {
#pragma unroll
            for (int sg = 0; sg < 2; sg++) {
                const unsigned short* lr = alp + r * (2 * SEG) + sg * SEG;
                const int cn = scp[r * 2 + sg];
                int i = 0;
                for (; i + 2 <= cn; i += 2) {
                    gather_half(g_W2T + (int)lr[i] * NPAD + base, L, cur[r], curs[r]);
                    gather_half(g_W2T + (int)lr[i + 1] * NPAD + base, L, cur[r], curs[r]);
                }
                if (i < cn)
                    gather_half(g_W2T + (int)lr[i] * NPAD + base, L, cur[r], curs[r]);
            }
        }

        // ---- LIF 2 (own half): packed update + 8-bit counters ----
#pragma unroll
        for (int r = 0; r < ROWS_PER_PAIR; r++) {
#pragma unroll
            for (int p = 0; p < 2; p++) {
                unsigned long long d = fsub2(cur[r][p], v2p[r][p]);
                unsigned long long vn = v2p[r][p];
                ffma2(vn, d, HALF2);
                float lo, hi;
                upk2(vn, lo, hi);
                bool s0 = (lo >= 1.0f), s1 = (hi >= 1.0f);
                v2p[r][p] = pk2(s0 ? 0.0f : lo, s1 ? 0.0f : hi);
                c2a[r] += s0 ? (1u << (8 * (2 * p))) : 0u;
                c2a[r] += s1 ? (1u << (8 * (2 * p + 1))) : 0u;
            }
            {
                float v = v2s[r] + (curs[r] - v2s[r]) * 0.5f;
                bool s = (v >= 1.0f);
                v2s[r] = s ? 0.0f : v;
                c2b[r] += s ? 1u : 0u;
            }
        }
    }

    // ---- epilogue: out[row] = counts @ W3^T + 101*b3 (pair-combined) ----
#pragma unroll
    for (int r = 0; r < ROWS_PER_PAIR; r++) {
        float acc[OUT_DIM];
#pragma unroll
        for (int o = 0; o < OUT_DIM; o++) acc[o] = 0.0f;
#pragma unroll
        for (int s = 0; s < 4; s++) {
            float c = (float)((c2a[r] >> (8 * s)) & 255u);
            int n = base + 4 * L + s;
            if (c != 0.0f) {
#pragma unroll
                for (int o = 0; o < OUT_DIM; o++)
                    acc[o] = fmaf(c, W3[o * HID + n], acc[o]);
            }
        }
        {
            float c = (float)(c2b[r] & 255u);
            int n = base + 128 + L;
            if (c != 0.0f && n < HID) {
#pragma unroll
                for (int o = 0; o < OUT_DIM; o++)
                    acc[o] = fmaf(c, W3[o * HID + n], acc[o]);
            }
        }
#pragma unroll
        for (int o = 0; o < OUT_DIM; o++) {
            float sv = acc[o];
            sv += __shfl_xor_sync(0xffffffffu, sv, 16);
            sv += __shfl_xor_sync(0xffffffffu, sv, 8);
            sv += __shfl_xor_sync(0xffffffffu, sv, 4);
            sv += __shfl_xor_sync(0xffffffffu, sv, 2);
            sv += __shfl_xor_sync(0xffffffffu, sv, 1);
            if (L == 0) obuf[((rl0 + r) * 2 + h) * OUT_DIM + o] = sv;
        }
    }
    pair_bar(pid);
    if (h == 1) {
#pragma unroll
        for (int r = 0; r < ROWS_PER_PAIR; r++) {
            if (L < OUT_DIM) {
                int rl = rl0 + r;
                float sv = obuf[(rl * 2 + 0) * OUT_DIM + L]
                         + obuf[(rl * 2 + 1) * OUT_DIM + L];
                out[(grow0 + r) * OUT_DIM + L] = sv + 101.0f * b3[L];
            }
        }
    }
}

extern "C" void kernel_launch(void* const* d_in, const int* in_sizes, int n_in,
                              void* d_out, int out_size) {
    const float* x  = (const float*)d_in[0];
    const float* W1 = (const float*)d_in[1];
    const float* b1 = (const float*)d_in[2];
    const float* Wh = (const float*)d_in[3];
    const float* bh = (const float*)d_in[4];
    const float* W2 = (const float*)d_in[5];
    const float* b2 = (const float*)d_in[6];
    const float* W3 = (const float*)d_in[7];
    const float* b3 = (const float*)d_in[8];
    float* out = (float*)d_out;

    {
        int total = HID * NPAD;
        int threads = 256;
        int blocks = (total + threads - 1) / threads;
        prep_kernel<<<blocks, threads>>>(Wh, W2);
    }

    size_t smem = (size_t)IN_DIM * NPAD * 4            // W1Ts
                + NPAD * 4 + NPAD * 4                   // bsum, b2s
                + (size_t)ROWS_PER_BLK * 2 * OUT_DIM * 4 // obuf
                + (size_t)ROWS_PER_BLK * 2 * SEG * 2     // lists
                + (size_t)ROWS_PER_BLK * 2 * 4;          // counts
    cudaFuncSetAttribute(snn_kernel, cudaFuncAttributeMaxDynamicSharedMemorySize,
                         (int)smem);
    snn_kernel<<<NUM_BLKS, THREADS_PER_BLK, smem>>>(x, W1, b1, bh, b2, W3, b3, out);
}

// round 8
// speedup vs baseline: 1.5149x; 1.5149x over previous
#include <cuda_runtime.h>
#include <cstdint>
#include <cstddef>

// Problem constants
#define T_STEPS   101
#define B_SZ      16384
#define IN_DIM    40
#define HID       300
#define NPAD      320
#define OUT_DIM   12

#define WARPS_PER_BLK   8
#define THREADS_PER_BLK 256
#define ROWS_PER_WARP   2
#define ROWS_PER_BLK    16
#define NUM_BLKS        (B_SZ / ROWS_PER_BLK)   // 1024
#define AL_STRIDE       304

// Transposed, padded recurrent/ff weights (global, L2-resident: 384KB each)
__device__ float g_WhT[HID * NPAD];   // g_WhT[k*NPAD + i] = Wh[i*HID + k]
__device__ float g_W2T[HID * NPAD];

__global__ void prep_kernel(const float* __restrict__ Wh,
                            const float* __restrict__ W2) {
    int idx = blockIdx.x * blockDim.x + threadIdx.x;
    const int total = HID * NPAD;
    if (idx < total) {
        int k = idx / NPAD;
        int i = idx % NPAD;
        float wh = 0.0f, w2 = 0.0f;
        if (i < HID) {
            wh = Wh[i * HID + k];
            w2 = W2[i * HID + k];
        }
        g_WhT[idx] = wh;
        g_W2T[idx] = w2;
    }
}

// ---- packed f32x2 helpers ----
__device__ __forceinline__ unsigned long long pk2(float lo, float hi) {
    unsigned long long r;
    asm("mov.b64 %0, {%1, %2};" : "=l"(r) : "f"(lo), "f"(hi));
    return r;
}
__device__ __forceinline__ void upk2(unsigned long long v, float& lo, float& hi) {
    asm("mov.b64 {%0, %1}, %2;" : "=f"(lo), "=f"(hi) : "l"(v));
}
__device__ __forceinline__ void ffma2(unsigned long long& acc,
                                      unsigned long long a, unsigned long long b) {
    asm("fma.rn.f32x2 %0, %1, %2, %0;" : "+l"(acc) : "l"(a), "l"(b));
}
__device__ __forceinline__ void fadd2(unsigned long long& acc, unsigned long long a) {
    asm("add.rn.f32x2 %0, %0, %1;" : "+l"(acc) : "l"(a));
}
__device__ __forceinline__ unsigned long long fsub2(unsigned long long a,
                                                    unsigned long long b) {
    unsigned long long d;
    asm("sub.rn.f32x2 %0, %1, %2;" : "=l"(d) : "l"(a), "l"(b));
    return d;
}

// Slot layout per lane L, per row:
//  ull q=0: neurons (4L,   4L+1)    q=1: (4L+2,   4L+3)     [0..127]
//  ull q=2: (160+4L, 160+4L+1)      q=3: (160+4L+2, +3)     [160..287]
//  f32 s=0: 128+L  [128..159]       s=1: 288+L  [288..319]
__device__ __forceinline__ int qbase(int q, int L) {
    return (q < 2) ? (4 * L + 2 * q) : (160 + 4 * L + 2 * (q - 2));
}

// gather-add one weight row into (q[4], s[2])
__device__ __forceinline__ void gather_row(const float* __restrict__ w0, int L,
                                           unsigned long long* q, float* s) {
    ulonglong2 g0 = *(const ulonglong2*)(w0 + 4 * L);
    ulonglong2 g1 = *(const ulonglong2*)(w0 + 160 + 4 * L);
    float gs0 = w0[128 + L];
    float gs1 = w0[288 + L];
    fadd2(q[0], g0.x); fadd2(q[1], g0.y);
    fadd2(q[2], g1.x); fadd2(q[3], g1.y);
    s[0] += gs0; s[1] += gs1;
}

__global__ void __launch_bounds__(THREADS_PER_BLK, 2)
snn_kernel(const float* __restrict__ x,
           const float* __restrict__ W1,
           const float* __restrict__ b1,
           const float* __restrict__ bh,
           const float* __restrict__ b2,
           const float* __restrict__ W3,
           const float* __restrict__ b3,
           float* __restrict__ out) {
    extern __shared__ char smem_raw[];
    float* W1Ts = (float*)smem_raw;                 // [IN_DIM][NPAD]  51200 B
    float* bsum = W1Ts + IN_DIM * NPAD;             // [NPAD]
    float* b2s  = bsum + NPAD;                      // [NPAD]
    float* h1buf = b2s + NPAD;                      // [8 warps][2 rows][NPAD]
    unsigned short* al = (unsigned short*)(h1buf + WARPS_PER_BLK * 2 * NPAD);
    // al: [16 rows][AL_STRIDE] u16

    const int tid = threadIdx.x;

    for (int idx = tid; idx < IN_DIM * NPAD; idx += THREADS_PER_BLK) {
        int k = idx / NPAD;
        int h = idx % NPAD;
        W1Ts[idx] = (h < HID) ? W1[h * IN_DIM + k] : 0.0f;
    }
    for (int n = tid; n < NPAD; n += THREADS_PER_BLK) {
        bsum[n] = (n < HID) ? (b1[n] + bh[n]) : 0.0f;
        b2s[n]  = (n < HID) ? b2[n] : 0.0f;
    }
    __syncthreads();

    const int w = tid >> 5;
    const int L = tid & 31;
    const int row0 = (blockIdx.x * WARPS_PER_BLK + w) * ROWS_PER_WARP;
    unsigned short* lst[ROWS_PER_WARP];
#pragma unroll
    for (int r = 0; r < ROWS_PER_WARP; r++)
        lst[r] = al + (w * ROWS_PER_WARP + r) * AL_STRIDE;
    float* h1w = h1buf + (w * 2) * NPAD;   // [2 rows][NPAD]

    // LIF states: per row 4 packed ulls + 2 scalars
    unsigned long long v1q[ROWS_PER_WARP][4], v2q[ROWS_PER_WARP][4];
    float v1s[ROWS_PER_WARP][2], v2s[ROWS_PER_WARP][2];
    unsigned long long curq[ROWS_PER_WARP][4];
    float curs[ROWS_PER_WARP][2];
    unsigned c2[ROWS_PER_WARP][3];
    int cnt[ROWS_PER_WARP];
#pragma unroll
    for (int r = 0; r < ROWS_PER_WARP; r++) {
#pragma unroll
        for (int q = 0; q < 4; q++) { v1q[r][q] = 0ull; v2q[r][q] = 0ull; }
        v1s[r][0] = v1s[r][1] = 0.0f;
        v2s[r][0] = v2s[r][1] = 0.0f;
        c2[r][0] = c2[r][1] = c2[r][2] = 0u;
        cnt[r] = 0;
    }
    const unsigned long long HALF2 = 0x3F0000003F000000ull;
    const unsigned lt_mask = (1u << L) - 1u;

    const float* xptr = x + (size_t)row0 * IN_DIM;
    const size_t xstep = (size_t)B_SZ * IN_DIM;

#pragma unroll 1
    for (int t = 0; t < T_STEPS; t += 2) {
        const bool has2 = (t + 1 < T_STEPS);

        // ---- x for 2 steps x 2 rows; combo c = step*2 + row ----
        float xa[4], xb[4];
#pragma unroll
        for (int r = 0; r < 2; r++) {
            xa[r] = xptr[r * IN_DIM + L];
            xb[r] = (L < 8) ? xptr[r * IN_DIM + 32 + L] : 0.0f;
            xa[2 + r] = has2 ? xptr[xstep + r * IN_DIM + L] : 0.0f;
            xb[2 + r] = (has2 && L < 8) ? xptr[xstep + r * IN_DIM + 32 + L] : 0.0f;
        }
        xptr += 2 * xstep;

        // ---- fused dense for both steps, two 160-neuron half-passes ----
#pragma unroll
        for (int hp = 0; hp < 2; hp++) {
            const int hb = hp * 160;
            ulonglong2 cA[4];
            float cS[4];
            {
                ulonglong2 bA = *(const ulonglong2*)(bsum + hb + 4 * L);
                float bS = bsum[hb + 128 + L];
#pragma unroll
                for (int c = 0; c < 4; c++) { cA[c] = bA; cS[c] = bS; }
            }
#pragma unroll 4
            for (int k = 0; k < 32; k++) {
                const float* wr = W1Ts + k * NPAD + hb;
                ulonglong2 wA = *(const ulonglong2*)(wr + 4 * L);
                float wS = wr[128 + L];
#pragma unroll
                for (int c = 0; c < 4; c++) {
                    float xv = __shfl_sync(0xffffffffu, xa[c], k);
                    unsigned long long xp = pk2(xv, xv);
                    ffma2(cA[c].x, xp, wA.x);
                    ffma2(cA[c].y, xp, wA.y);
                    cS[c] = fmaf(xv, wS, cS[c]);
                }
            }
#pragma unroll
            for (int k = 0; k < 8; k++) {
                const float* wr = W1Ts + (32 + k) * NPAD + hb;
                ulonglong2 wA = *(const ulonglong2*)(wr + 4 * L);
                float wS = wr[128 + L];
#pragma unroll
                for (int c = 0; c < 4; c++) {
                    float xv = __shfl_sync(0xffffffffu, xb[c], k);
                    unsigned long long xp = pk2(xv, xv);
                    ffma2(cA[c].x, xp, wA.x);
                    ffma2(cA[c].y, xp, wA.y);
                    cS[c] = fmaf(xv, wS, cS[c]);
                }
            }
            // step t results -> registers
#pragma unroll
            for (int r = 0; r < 2; r++) {
                curq[r][2 * hp]     = cA[r].x;
                curq[r][2 * hp + 1] = cA[r].y;
                curs[r][hp]         = cS[r];
            }
            // step t+1 results -> smem stash
#pragma unroll
            for (int r = 0; r < 2; r++) {
                *(ulonglong2*)(h1w + r * NPAD + hb + 4 * L) = cA[2 + r];
                h1w[r * NPAD + hb + 128 + L] = cS[2 + r];
            }
        }

        // ---- process step t, then step t+1 ----
#pragma unroll 1
        for (int ss = 0; ss < 2; ss++) {
            if (ss == 1) {
                if (!has2) break;
                // load step t+1 currents from stash
#pragma unroll
                for (int r = 0; r < 2; r++) {
                    ulonglong2 a0 = *(const ulonglong2*)(h1w + r * NPAD + 4 * L);
                    ulonglong2 a1 = *(const ulonglong2*)(h1w + r * NPAD + 160 + 4 * L);
                    curq[r][0] = a0.x; curq[r][1] = a0.y;
                    curq[r][2] = a1.x; curq[r][3] = a1.y;
                    curs[r][0] = h1w[r * NPAD + 128 + L];
                    curs[r][1] = h1w[r * NPAD + 288 + L];
                }
            }

            // ---- recurrent gathers (prev-step lists) ----
#pragma unroll
            for (int r = 0; r < 2; r++) {
                const unsigned short* lr = lst[r];
                const int cn = cnt[r];
                int i = 0;
                for (; i + 2 <= cn; i += 2) {
                    gather_row(g_WhT + (int)lr[i] * NPAD, L, curq[r], curs[r]);
                    gather_row(g_WhT + (int)lr[i + 1] * NPAD, L, curq[r], curs[r]);
                }
                if (i < cn)
                    gather_row(g_WhT + (int)lr[i] * NPAD, L, curq[r], curs[r]);
            }
            __syncwarp();

            // ---- LIF 1 + rebuild spike lists ----
#pragma unroll
            for (int r = 0; r < 2; r++) {
                int nc = 0;
#pragma unroll
                for (int q = 0; q < 4; q++) {
                    unsigned long long d = fsub2(curq[r][q], v1q[r][q]);
                    unsigned long long vn = v1q[r][q];
                    ffma2(vn, d, HALF2);
                    float lo, hi;
                    upk2(vn, lo, hi);
                    bool s0 = (lo >= 1.0f), s1 = (hi >= 1.0f);
                    v1q[r][q] = pk2(s0 ? 0.0f : lo, s1 ? 0.0f : hi);
                    int nb = qbase(q, L);
                    unsigned m0 = __ballot_sync(0xffffffffu, s0);
                    if (s0) lst[r][nc + __popc(m0 & lt_mask)] = (unsigned short)nb;
                    nc += __popc(m0);
                    unsigned m1 = __ballot_sync(0xffffffffu, s1);
                    if (s1) lst[r][nc + __popc(m1 & lt_mask)] = (unsigned short)(nb + 1);
                    nc += __popc(m1);
                }
#pragma unroll
                for (int s = 0; s < 2; s++) {
                    float v = v1s[r][s] + (curs[r][s] - v1s[r][s]) * 0.5f;
                    bool sp = (v >= 1.0f);
                    v1s[r][s] = sp ? 0.0f : v;
                    int nb = s ? (288 + L) : (128 + L);
                    unsigned m = __ballot_sync(0xffffffffu, sp);
                    if (sp) lst[r][nc + __popc(m & lt_mask)] = (unsigned short)nb;
                    nc += __popc(m);
                }
                cnt[r] = nc;
            }
            __syncwarp();

            // ---- layer 2: bias + gathers ----
            {
                ulonglong2 bA = *(const ulonglong2*)(b2s + 4 * L);
                ulonglong2 bB = *(const ulonglong2*)(b2s + 160 + 4 * L);
                float bS0 = b2s[128 + L];
                float bS1 = b2s[288 + L];
#pragma unroll
                for (int r = 0; r < 2; r++) {
                    curq[r][0] = bA.x; curq[r][1] = bA.y;
                    curq[r][2] = bB.x; curq[r][3] = bB.y;
                    curs[r][0] = bS0;  curs[r][1] = bS1;
                }
            }
#pragma unroll
            for (int r = 0; r < 2; r++) {
                const unsigned short* lr = lst[r];
                const int cn = cnt[r];
                int i = 0;
                for (; i + 2 <= cn; i += 2) {
                    gather_row(g_W2T + (int)lr[i] * NPAD, L, curq[r], curs[r]);
                    gather_row(g_W2T + (int)lr[i + 1] * NPAD, L, curq[r], curs[r]);
                }
                if (i < cn)
                    gather_row(g_W2T + (int)lr[i] * NPAD, L, curq[r], curs[r]);
            }

            // ---- LIF 2: packed update + 8-bit spike counters ----
#pragma unroll
            for (int r = 0; r < 2; r++) {
#pragma unroll
                for (int q = 0; q < 4; q++) {
                    unsigned long long d = fsub2(curq[r][q], v2q[r][q]);
                    unsigned long long vn = v2q[r][q];
                    ffma2(vn, d, HALF2);
                    float lo, hi;
                    upk2(vn, lo, hi);
                    bool s0 = (lo >= 1.0f), s1 = (hi >= 1.0f);
                    v2q[r][q] = pk2(s0 ? 0.0f : lo, s1 ? 0.0f : hi);
                    int byte0 = 2 * (q & 1);
                    c2[r][q >> 1] += s0 ? (1u << (8 * byte0)) : 0u;
                    c2[r][q >> 1] += s1 ? (1u << (8 * (byte0 + 1))) : 0u;
                }
#pragma unroll
                for (int s = 0; s < 2; s++) {
                    float v = v2s[r][s] + (curs[r][s] - v2s[r][s]) * 0.5f;
                    bool sp = (v >= 1.0f);
                    v2s[r][s] = sp ? 0.0f : v;
                    c2[r][2] += sp ? (1u << (8 * s)) : 0u;
                }
            }
        }
    }

    // ---- epilogue: out[row] = counts @ W3^T + 101*b3 ----
#pragma unroll
    for (int r = 0; r < ROWS_PER_WARP; r++) {
        float acc[OUT_DIM];
#pragma unroll
        for (int o = 0; o < OUT_DIM; o++) acc[o] = 0.0f;
#pragma unroll
        for (int q = 0; q < 4; q++) {
#pragma unroll
            for (int e = 0; e < 2; e++) {
                int n = qbase(q, L) + e;
                float c = (float)((c2[r][q >> 1] >> (8 * (2 * (q & 1) + e))) & 255u);
                if (c != 0.0f) {
#pragma unroll
                    for (int o = 0; o < OUT_DIM; o++)
                        acc[o] = fmaf(c, W3[o * HID + n], acc[o]);
                }
            }
        }
#pragma unroll
        for (int s = 0; s < 2; s++) {
            int n = s ? (288 + L) : (128 + L);
            float c = (float)((c2[r][2] >> (8 * s)) & 255u);
            if (c != 0.0f && n < HID) {
#pragma unroll
                for (int o = 0; o < OUT_DIM; o++)
                    acc[o] = fmaf(c, W3[o * HID + n], acc[o]);
            }
        }
#pragma unroll
        for (int o = 0; o < OUT_DIM; o++) {
            float sv = acc[o];
            sv += __shfl_xor_sync(0xffffffffu, sv, 16);
            sv += __shfl_xor_sync(0xffffffffu, sv, 8);
            sv += __shfl_xor_sync(0xffffffffu, sv, 4);
            sv += __shfl_xor_sync(0xffffffffu, sv, 2);
            sv += __shfl_xor_sync(0xffffffffu, sv, 1);
            if (L == 0) out[(row0 + r) * OUT_DIM + o] = sv + 101.0f * b3[o];
        }
    }
}

extern "C" void kernel_launch(void* const* d_in, const int* in_sizes, int n_in,
                              void* d_out, int out_size) {
    const float* x  = (const float*)d_in[0];
    const float* W1 = (const float*)d_in[1];
    const float* b1 = (const float*)d_in[2];
    const float* Wh = (const float*)d_in[3];
    const float* bh = (const float*)d_in[4];
    const float* W2 = (const float*)d_in[5];
    const float* b2 = (const float*)d_in[6];
    const float* W3 = (const float*)d_in[7];
    const float* b3 = (const float*)d_in[8];
    float* out = (float*)d_out;

    {
        int total = HID * NPAD;
        int threads = 256;
        int blocks = (total + threads - 1) / threads;
        prep_kernel<<<blocks, threads>>>(Wh, W2);
    }

    size_t smem = (size_t)IN_DIM * NPAD * 4            // W1Ts
                + NPAD * 4 + NPAD * 4                   // bsum, b2s
                + (size_t)WARPS_PER_BLK * 2 * NPAD * 4  // h1buf
                + (size_t)ROWS_PER_BLK * AL_STRIDE * 2; // lists
    cudaFuncSetAttribute(snn_kernel, cudaFuncAttributeMaxDynamicSharedMemorySize,
                         (int)smem);
    snn_kernel<<<NUM_BLKS, THREADS_PER_BLK, smem>>>(x, W1, b1, bh, b2, W3, b3, out);
}